// round 12
// baseline (speedup 1.0000x reference)
#include <cuda_runtime.h>
#include <cuda_bf16.h>
#include <mma.h>
#include <cstdint>

using namespace nvcuda;

#define VOCAB   50257
#define M_TOK   4096
#define K_HID   1024
#define N_PAD   50304          // 393 * 128
#define NT      393
#define PARTW   400
#define NCLUST  3

// ---------------- scratch ----------------
__device__ __align__(128) __nv_bfloat16 g_xp[(size_t)M_TOK * K_HID];   // x bf16, ROWS PERMUTED (sorted order)
__device__ __align__(128) __nv_bfloat16 g_lb[(size_t)K_HID * N_PAD];   // logits bf16 [K][N_PAD]
__device__ float g_part[(size_t)M_TOK * PARTW];
__device__ int   g_perm[M_TOK];
__device__ int   g_tokcl[M_TOK];
__device__ int   g_yint[M_TOK];
__device__ int   g_cfirst[M_TOK / 128];
__device__ int   g_clast[M_TOK / 128];

// ---------------- k_sort: decode y (int32/int64), group tokens by cluster ----------------
__global__ void k_sort(const int* __restrict__ y32) {
    __shared__ int cnt[NCLUST], cur[NCLUST];
    __shared__ int is64;
    int tid = threadIdx.x;
    if (tid == 0) {
        int odd = 0;
        for (int i = 0; i < 64; i++) odd |= y32[2 * i + 1];
        is64 = (odd == 0) ? 1 : 0;
    }
    if (tid < NCLUST) cnt[tid] = 0;
    __syncthreads();
    for (int t = tid; t < M_TOK; t += 1024) {
        int yi = is64 ? y32[2 * t] : y32[t];
        yi = max(0, min(VOCAB - 1, yi));
        g_yint[t] = yi;
        int c = yi < 20000 ? 0 : (yi < 40000 ? 1 : 2);
        g_tokcl[t] = c;
        atomicAdd(&cnt[c], 1);
    }
    __syncthreads();
    if (tid == 0) { cur[0] = 0; cur[1] = cnt[0]; cur[2] = cnt[0] + cnt[1]; }
    __syncthreads();
    for (int t = tid; t < M_TOK; t += 1024) {
        int pos = atomicAdd(&cur[g_tokcl[t]], 1);
        g_perm[pos] = t;
    }
    __syncthreads();
    if (tid < M_TOK / 128) {
        g_cfirst[tid] = g_tokcl[g_perm[tid * 128]];
        g_clast[tid]  = g_tokcl[g_perm[tid * 128 + 127]];
    }
}

// ---------------- k_permx: x f32 -> bf16, rows gathered into sorted order ----------------
// (runs AFTER k_sort). 128 threads per row, 8 halves each.
__global__ void k_permx(const float* __restrict__ x) {
    int t = blockIdx.x * 256 + threadIdx.x;          // 0 .. 524287
    int r = t >> 7, seg = t & 127;                   // sorted row, 8-half segment
    const float* src = x + (size_t)g_perm[r] * K_HID + seg * 8;
    union { __nv_bfloat16 h[8]; uint4 u; } p;
#pragma unroll
    for (int i = 0; i < 8; i++) p.h[i] = __float2bfloat16(src[i]);
    *(uint4*)(g_xp + (size_t)r * K_HID + seg * 8) = p.u;
}

// ---------------- k_prep_l: logits f32 [K][VOCAB] -> bf16 [K][N_PAD], 2 cols/thread ----------------
__global__ void k_prep_l(const float* __restrict__ logits) {
    int c2  = blockIdx.x * 128 + threadIdx.x;
    int k   = blockIdx.y;
    int col = c2 * 2;
    const float* row = logits + (size_t)k * VOCAB;
    float v0 = (col     < VOCAB) ? row[col]     : 0.0f;
    float v1 = (col + 1 < VOCAB) ? row[col + 1] : 0.0f;
    __nv_bfloat162 p;
    p.x = __float2bfloat16(v0);
    p.y = __float2bfloat16(v1);
    *(__nv_bfloat162*)(g_lb + (size_t)k * N_PAD + col) = p;
}

// ---------------- k_gemm: WMMA bf16, fragments loaded DIRECT FROM GMEM (no smem mainloop) ----------------
#define P_PITCH 72     // floats per patch row
struct __align__(128) SmemE {
    __align__(128) float patch[4][16 * P_PITCH];     // 18432 B
    float ep[128][2];                                //  1024 B
    int rowperm[128];
    int rowcl[128];
};

__global__ __launch_bounds__(128, 2) void k_gemm() {
    const int m_tile = blockIdx.x, n_tile = blockIdx.y;
    const int TB[NCLUST] = {0, 156, 312};
    const int TE[NCLUST] = {157, 313, 393};
    {
        int cf = g_cfirst[m_tile], cl = g_clast[m_tile];
        if (n_tile < TB[cf] || n_tile >= TE[cl]) return;
    }

    __shared__ SmemE s;
    const int tid = threadIdx.x, lane = tid & 31, wid = tid >> 5;
    const int wm = wid >> 1, wn = wid & 1;           // 2(m) x 2(n) warps, 64x64 each

    {
        int o = g_perm[m_tile * 128 + tid];
        s.rowperm[tid] = o;
        s.rowcl[tid] = g_tokcl[o];
    }

    wmma::fragment<wmma::accumulator, 16, 16, 16, float> acc[4][4];
#pragma unroll
    for (int fm = 0; fm < 4; fm++)
#pragma unroll
        for (int fn = 0; fn < 4; fn++) wmma::fill_fragment(acc[fm][fn], 0.0f);

    // A: sorted rows, this warp's 64-row band.  B: [k][N_PAD], this warp's 64-col band.
    const __nv_bfloat16* Abase = g_xp + (size_t)(m_tile * 128 + wm * 64) * K_HID;
    const __nv_bfloat16* Bbase = g_lb + (size_t)n_tile * 128 + wn * 64;

#pragma unroll 1
    for (int k16 = 0; k16 < K_HID / 16; k16++) {
        const size_t ka = (size_t)k16 * 16;
        wmma::fragment<wmma::matrix_b, 16, 16, 16, __nv_bfloat16, wmma::row_major> bf[4];
#pragma unroll
        for (int fn = 0; fn < 4; fn++)
            wmma::load_matrix_sync(bf[fn], Bbase + ka * N_PAD + fn * 16, N_PAD);
#pragma unroll
        for (int fm = 0; fm < 4; fm++) {
            wmma::fragment<wmma::matrix_a, 16, 16, 16, __nv_bfloat16, wmma::row_major> af;
            wmma::load_matrix_sync(af, Abase + (size_t)(fm * 16) * K_HID + ka, K_HID);
#pragma unroll
            for (int fn = 0; fn < 4; fn++)
                wmma::mma_sync(acc[fm][fn], af, bf[fn], acc[fm][fn]);
        }
    }
    __syncthreads();    // rowperm/rowcl visible; no other mainloop syncs existed

    // Epilogue: exp + cluster-masked row sums, deterministic fixed order.
    const int r16 = lane & 15, cg = lane >> 4;
    const int vbase = n_tile * 128 + wn * 64 + cg * 32;
#pragma unroll
    for (int fm = 0; fm < 4; fm++) {
        __syncwarp();
#pragma unroll
        for (int fn = 0; fn < 4; fn++)
            wmma::store_matrix_sync(&s.patch[wid][fn * 16], acc[fm][fn],
                                    P_PITCH, wmma::mem_row_major);
        __syncwarp();
        int rloc = wm * 64 + fm * 16 + r16;
        int crow = s.rowcl[rloc];
        float sum = 0.0f;
#pragma unroll
        for (int j = 0; j < 32; j++) {
            int vc = vbase + j;
            int ccol = vc < 20000 ? 0 : (vc < 40000 ? 1 : (vc < VOCAB ? 2 : 3));
            float v = s.patch[wid][r16 * P_PITCH + cg * 32 + j];
            if (ccol == crow) sum += __expf(v);
        }
        sum += __shfl_xor_sync(0xffffffffu, sum, 16);
        if (lane < 16) s.ep[rloc][wn] = sum;
        __syncwarp();
    }
    __syncthreads();
    {
        float tot = s.ep[tid][0] + s.ep[tid][1];     // fixed order
        g_part[(size_t)s.rowperm[tid] * PARTW + n_tile] = tot;
    }
}

// ---------------- k_final: per-token NLL (fp32), one warp per token ----------------
__global__ void k_final(const float* __restrict__ x,
                        const float* __restrict__ Wc, const float* __restrict__ logits,
                        float* __restrict__ out) {
    const int TB[NCLUST] = {0, 156, 312};
    const int TE[NCLUST] = {157, 313, 393};
    int warp = threadIdx.x >> 5, lane = threadIdx.x & 31;
    int token = blockIdx.x * 8 + warp;
    const float* xr = x + (size_t)token * K_HID;

    float xv[32];
#pragma unroll
    for (int i = 0; i < 32; i++) xv[i] = xr[i * 32 + lane];

    float s0 = 0.f, s1 = 0.f, s2 = 0.f;
#pragma unroll
    for (int i = 0; i < 32; i++) {
        int h = i * 32 + lane;
        s0 = fmaf(xv[i], Wc[h], s0);
        s1 = fmaf(xv[i], Wc[K_HID + h], s1);
        s2 = fmaf(xv[i], Wc[2 * K_HID + h], s2);
    }

    int yi = g_yint[token];
    int c  = g_tokcl[token];
    float tg = 0.f;
#pragma unroll
    for (int i = 0; i < 32; i++) {
        int h = i * 32 + lane;
        tg = fmaf(xv[i], logits[(size_t)h * VOCAB + yi], tg);
    }

    float se = 0.f;
    for (int t = TB[c] + lane; t < TE[c]; t += 32)
        se += g_part[(size_t)token * PARTW + t];

#pragma unroll
    for (int o = 16; o; o >>= 1) {
        s0 += __shfl_xor_sync(0xffffffffu, s0, o);
        s1 += __shfl_xor_sync(0xffffffffu, s1, o);
        s2 += __shfl_xor_sync(0xffffffffu, s2, o);
        tg += __shfl_xor_sync(0xffffffffu, tg, o);
        se += __shfl_xor_sync(0xffffffffu, se, o);
    }

    if (lane == 0) {
        float m = fmaxf(s0, fmaxf(s1, s2));
        float lse3 = m + logf(expf(s0 - m) + expf(s1 - m) + expf(s2 - m));
        float sc = (c == 0) ? s0 : ((c == 1) ? s1 : s2);
        out[token] = -(sc - lse3) - (tg - logf(se));
    }
}

// ---------------- launch ----------------
extern "C" void kernel_launch(void* const* d_in, const int* in_sizes, int n_in,
                              void* d_out, int out_size) {
    const float* x      = (const float*)d_in[0];
    const int*   y32    = (const int*)d_in[1];
    const float* Wc     = (const float*)d_in[2];
    const float* logits = (const float*)d_in[3];
    float*       out    = (float*)d_out;

    k_sort<<<1, 1024>>>(y32);                                // perm first (k_permx needs it)
    k_permx<<<M_TOK * K_HID / (256 * 8), 256>>>(x);          // x -> bf16, sorted rows
    k_prep_l<<<dim3(N_PAD / 256, K_HID), 128>>>(logits);
    k_gemm<<<dim3(M_TOK / 128, NT), 128>>>();                // m fastest -> B stripe L2-resident
    k_final<<<M_TOK / 8, 256>>>(x, Wc, logits, out);
}